// round 9
// baseline (speedup 1.0000x reference)
#include <cuda_runtime.h>
#include <cuda_fp16.h>
#include <cstdint>

#define NN 100000
#define EE 1600000
#define DD 128
#define NBLK ((NN + 1023) / 1024)   // 98 scan blocks

// ---------------- static device scratch (no allocation allowed) ----------------
__device__ __half g_xh[NN * DD];        // x * inv[row], half
__device__ __half g_aggh[NN * DD];      // gather output, half
__device__ __half g_hh[NN * DD];        // layer-1 output * inv[row], half
__device__ uint2  g_wfrag1[8 * 16 * 32];  // W1 f16 B-fragment table (32KB)
__device__ uint2  g_wfrag2[8 * 16 * 32];  // W2 fragment table
__device__ int    g_outdeg[NN];
__device__ int    g_indeg[NN];
__device__ int    g_rowptr[NN + 1];
__device__ int    g_cursor[NN];
__device__ int    g_colidx[EE];
__device__ float  g_inv[NN];
__device__ unsigned long long g_state[NBLK];   // scan aggregates (sentinel = all-ones)

#define MMA_F16(c0, c1, c2, c3, a0, a1, a2, a3, b0, b1) \
    asm volatile("mma.sync.aligned.m16n8k16.row.col.f32.f16.f16.f32 " \
        "{%0,%1,%2,%3}, {%4,%5,%6,%7}, {%8,%9}, {%0,%1,%2,%3};" \
        : "+f"(c0), "+f"(c1), "+f"(c2), "+f"(c3) \
        : "r"(a0), "r"(a1), "r"(a2), "r"(a3), "r"(b0), "r"(b1))

__device__ __forceinline__ uint32_t h2bits(__half2 h) {
    return *(uint32_t*)&h;
}

// ---------------- build: degrees ----------------
__global__ void k_deg(const int* __restrict__ src, const int* __restrict__ dst, int E) {
    int e = blockIdx.x * blockDim.x + threadIdx.x;
    if (e < E) {
        atomicAdd(&g_outdeg[src[e]], 1);
        atomicAdd(&g_indeg[dst[e]], 1);
    }
}

// ---------------- build: single-kernel scan (aggregate lookback) ----------------
// 98 blocks, all resident simultaneously. Each block scans its 1024-chunk,
// publishes its aggregate, then warp-parallel sums ALL predecessor aggregates
// (no chained prefix -> no serialization). Writes rowptr, cursor, inv.
#define SENT 0xFFFFFFFFFFFFFFFFull
__global__ __launch_bounds__(1024, 1)
void k_scan(int N, int E) {
    __shared__ int s_w[32];
    __shared__ int s_off;
    int tid = threadIdx.x, lane = tid & 31, wid = tid >> 5;
    int bid = blockIdx.x;
    int i = bid * 1024 + tid;
    int v = (i < N) ? g_indeg[i] : 0;
    int incl = v;
#pragma unroll
    for (int off = 1; off < 32; off <<= 1) {
        int t = __shfl_up_sync(0xffffffffu, incl, off);
        if (lane >= off) incl += t;
    }
    if (lane == 31) s_w[wid] = incl;
    __syncthreads();
    if (wid == 0) {
        int s = s_w[lane];
        int si = s;
#pragma unroll
        for (int off = 1; off < 32; off <<= 1) {
            int t = __shfl_up_sync(0xffffffffu, si, off);
            if (lane >= off) si += t;
        }
        s_w[lane] = si - s;            // exclusive prefix of warp sums
        if (lane == 31) {
            // si == block total; publish aggregate
            atomicExch(&g_state[bid], (unsigned long long)si);
        }
    }
    __syncthreads();
    int excl_in_blk = incl - v + s_w[wid];

    // Lookback: warp 0 sums all predecessor aggregates (32 at a time).
    if (wid == 0) {
        long long sum = 0;
        for (int base = bid - 1; base >= 0; base -= 32) {
            int idx = base - lane;
            unsigned long long s = 0;
            if (idx >= 0) {
                do { s = atomicAdd(&g_state[idx], 0ull); } while (s == SENT);
            }
            long long x = (idx >= 0) ? (long long)s : 0;
#pragma unroll
            for (int o = 16; o > 0; o >>= 1)
                x += __shfl_down_sync(0xffffffffu, x, o);
            x = __shfl_sync(0xffffffffu, x, 0);
            sum += x;
        }
        if (lane == 0) s_off = (int)sum;
    }
    __syncthreads();

    if (i < N) {
        int val = excl_in_blk + s_off;
        g_rowptr[i] = val;
        g_cursor[i] = val;
        int d = g_outdeg[i];
        g_inv[i] = 1.0f / (float)(d > 1 ? d : 1);
    }
    if (bid == 0 && tid == 0) g_rowptr[N] = E;
}

// ---------------- merged scatter + x->half + wfrag pack (all post-scan, independent) ----------------
#define SCAT_BLK ((EE + 255) / 256)        // 6250
#define TOH_BLK  ((NN * 32 + 255) / 256)   // 12500
__global__ void k_build2(const int* __restrict__ src, const int* __restrict__ dst,
                         const float4* __restrict__ x, uint2* __restrict__ xh,
                         const float* __restrict__ W1, uint2* __restrict__ f1,
                         const float* __restrict__ W2, uint2* __restrict__ f2,
                         int E, int N) {
    int b = blockIdx.x;
    if (b < SCAT_BLK) {
        int e = b * 256 + threadIdx.x;
        if (e < E) {
            int p = atomicAdd(&g_cursor[dst[e]], 1);
            g_colidx[p] = src[e];
        }
    } else if (b < SCAT_BLK + TOH_BLK) {
        int i = (b - SCAT_BLK) * 256 + threadIdx.x;
        if (i < N * 32) {
            float s = g_inv[i >> 5];
            float4 v = x[i];
            __half2 h01 = __floats2half2_rn(v.x * s, v.y * s);
            __half2 h23 = __floats2half2_rn(v.z * s, v.w * s);
            xh[i] = make_uint2(h2bits(h01), h2bits(h23));
        }
    } else {
        int gb = b - SCAT_BLK - TOH_BLK;   // 0..31
        const float* W = (gb < 16) ? W1 : W2;
        uint2* frag = (gb < 16) ? f1 : f2;
        int idx = (gb & 15) * 256 + threadIdx.x;   // 0..4095
        int lane = idx & 31, nt = (idx >> 5) & 15, ks = idx >> 9;
        int k0 = ks * 16, col = nt * 8 + (lane >> 2), r = lane & 3;
        __half2 b0 = __floats2half2_rn(W[(k0 + 2 * r) * DD + col], W[(k0 + 2 * r + 1) * DD + col]);
        __half2 b1 = __floats2half2_rn(W[(k0 + 2 * r + 8) * DD + col], W[(k0 + 2 * r + 9) * DD + col]);
        frag[idx] = make_uint2(h2bits(b0), h2bits(b1));
    }
}

// ---------------- SpMM gather (half features, plain sum, unroll x4) ----------------
__global__ void k_gather(const uint2* __restrict__ xin, uint2* __restrict__ out, int N) {
    int lane = threadIdx.x;
    int node = blockIdx.x * blockDim.y + threadIdx.y;
    if (node >= N) return;
    int beg = g_rowptr[node], end = g_rowptr[node + 1];
    float4 a0 = make_float4(0.f, 0.f, 0.f, 0.f);
    float4 a1 = make_float4(0.f, 0.f, 0.f, 0.f);
    int e = beg;
#pragma unroll 1
    for (; e + 4 <= end; e += 4) {
        int s0 = g_colidx[e + 0];
        int s1 = g_colidx[e + 1];
        int s2 = g_colidx[e + 2];
        int s3 = g_colidx[e + 3];
        uint2 v0 = xin[s0 * 32 + lane];
        uint2 v1 = xin[s1 * 32 + lane];
        uint2 v2 = xin[s2 * 32 + lane];
        uint2 v3 = xin[s3 * 32 + lane];
        float2 f;
        f = __half22float2(*(__half2*)&v0.x); a0.x += f.x; a0.y += f.y;
        f = __half22float2(*(__half2*)&v0.y); a0.z += f.x; a0.w += f.y;
        f = __half22float2(*(__half2*)&v1.x); a1.x += f.x; a1.y += f.y;
        f = __half22float2(*(__half2*)&v1.y); a1.z += f.x; a1.w += f.y;
        f = __half22float2(*(__half2*)&v2.x); a0.x += f.x; a0.y += f.y;
        f = __half22float2(*(__half2*)&v2.y); a0.z += f.x; a0.w += f.y;
        f = __half22float2(*(__half2*)&v3.x); a1.x += f.x; a1.y += f.y;
        f = __half22float2(*(__half2*)&v3.y); a1.z += f.x; a1.w += f.y;
    }
    for (; e < end; e++) {
        int s = g_colidx[e];
        uint2 v = xin[s * 32 + lane];
        float2 f;
        f = __half22float2(*(__half2*)&v.x); a0.x += f.x; a0.y += f.y;
        f = __half22float2(*(__half2*)&v.y); a0.z += f.x; a0.w += f.y;
    }
    a0.x += a1.x; a0.y += a1.y; a0.z += a1.z; a0.w += a1.w;
    __half2 h01 = __floats2half2_rn(a0.x, a0.y);
    __half2 h23 = __floats2half2_rn(a0.z, a0.w);
    out[node * 32 + lane] = make_uint2(h2bits(h01), h2bits(h23));
}

// ---------------- f16 mma GEMM + bias + PReLU ----------------
// CTA: 128 rows x 128 cols, 8 warps, warp tile 32x64 (2 m-groups share each B frag).
#define ASTRH 136    // half stride: conflict-free A-frag LDS
template <bool HALF_OUT>
__global__ __launch_bounds__(256, 2)
void k_gemm_mma(const __half* __restrict__ A, const uint2* __restrict__ wfrag,
                const float* __restrict__ bias, const float* __restrict__ pa,
                void* __restrict__ outp, int N) {
    __shared__ __align__(16) __half As[128 * ASTRH];
    int tid = threadIdx.x;
    int lane = tid & 31, wid = tid >> 5;
    int rowgrp = wid & 3, colgrp = wid >> 2;
    int rbase = blockIdx.x * 128;

    const uint2* A2 = (const uint2*)A;
#pragma unroll 4
    for (int i = tid; i < 128 * 32; i += 256) {
        int r = i >> 5, c4 = i & 31;
        int row = rbase + r;
        if (row >= N) row = N - 1;   // clamp; extra rows never stored
        *(uint2*)&As[r * ASTRH + c4 * 4] = A2[row * 32 + c4];
    }
    __syncthreads();

    float c[2][8][4];
#pragma unroll
    for (int mg = 0; mg < 2; mg++)
#pragma unroll
        for (int nt = 0; nt < 8; nt++)
#pragma unroll
            for (int j = 0; j < 4; j++) c[mg][nt][j] = 0.f;

    const __half* Ab0 = As + (rowgrp * 32 + (lane >> 2)) * ASTRH + 2 * (lane & 3);
    const __half* Ab1 = Ab0 + 16 * ASTRH;

#pragma unroll
    for (int ks = 0; ks < 8; ks++) {
        int k0 = ks * 16;
        uint32_t a00 = *(const uint32_t*)&Ab0[k0];
        uint32_t a01 = *(const uint32_t*)&Ab0[8 * ASTRH + k0];
        uint32_t a02 = *(const uint32_t*)&Ab0[k0 + 8];
        uint32_t a03 = *(const uint32_t*)&Ab0[8 * ASTRH + k0 + 8];
        uint32_t a10 = *(const uint32_t*)&Ab1[k0];
        uint32_t a11 = *(const uint32_t*)&Ab1[8 * ASTRH + k0];
        uint32_t a12 = *(const uint32_t*)&Ab1[k0 + 8];
        uint32_t a13 = *(const uint32_t*)&Ab1[8 * ASTRH + k0 + 8];
        const uint2* wk = wfrag + (ks * 16 + colgrp * 8) * 32 + lane;
#pragma unroll
        for (int nt = 0; nt < 8; nt++) {
            uint2 bv = wk[nt * 32];
            MMA_F16(c[0][nt][0], c[0][nt][1], c[0][nt][2], c[0][nt][3],
                    a00, a01, a02, a03, bv.x, bv.y);
            MMA_F16(c[1][nt][0], c[1][nt][1], c[1][nt][2], c[1][nt][3],
                    a10, a11, a12, a13, bv.x, bv.y);
        }
    }

    float alpha = pa[0];
#pragma unroll
    for (int mg = 0; mg < 2; mg++) {
        int r_lo = rbase + rowgrp * 32 + mg * 16 + (lane >> 2);
        int r_hi = r_lo + 8;
        float s_lo = 1.f, s_hi = 1.f;
        if (HALF_OUT) {
            if (r_lo < N) s_lo = g_inv[r_lo];
            if (r_hi < N) s_hi = g_inv[r_hi];
        }
#pragma unroll
        for (int nt = 0; nt < 8; nt++) {
            int col = colgrp * 64 + nt * 8 + (lane & 3) * 2;
            float2 bb = *(const float2*)(bias + col);
            float z0 = c[mg][nt][0] + bb.x;
            float z1 = c[mg][nt][1] + bb.y;
            float z2 = c[mg][nt][2] + bb.x;
            float z3 = c[mg][nt][3] + bb.y;
            z0 = (z0 >= 0.f) ? z0 : alpha * z0;
            z1 = (z1 >= 0.f) ? z1 : alpha * z1;
            z2 = (z2 >= 0.f) ? z2 : alpha * z2;
            z3 = (z3 >= 0.f) ? z3 : alpha * z3;
            if (HALF_OUT) {
                __half* outh = (__half*)outp;
                if (r_lo < N) {
                    __half2 o = __floats2half2_rn(z0 * s_lo, z1 * s_lo);
                    *(__half2*)(outh + r_lo * DD + col) = o;
                }
                if (r_hi < N) {
                    __half2 o = __floats2half2_rn(z2 * s_hi, z3 * s_hi);
                    *(__half2*)(outh + r_hi * DD + col) = o;
                }
            } else {
                float* outf = (float*)outp;
                if (r_lo < N) { float2 o = {z0, z1}; *(float2*)(outf + r_lo * DD + col) = o; }
                if (r_hi < N) { float2 o = {z2, z3}; *(float2*)(outf + r_hi * DD + col) = o; }
            }
        }
    }
}

// ---------------- launch ----------------
extern "C" void kernel_launch(void* const* d_in, const int* in_sizes, int n_in,
                              void* d_out, int out_size) {
    const float* x   = (const float*)d_in[0];
    const int*   src = (const int*)d_in[1];
    const int*   dst = (const int*)d_in[2];
    const float* W1  = (const float*)d_in[3];
    const float* b1  = (const float*)d_in[4];
    const float* W2  = (const float*)d_in[5];
    const float* b2  = (const float*)d_in[6];
    const float* pa  = (const float*)d_in[7];
    float* out = (float*)d_out;

    const int N = NN;
    const int E = EE;

    __half *xh, *aggh, *hh;
    uint2 *wf1, *wf2;
    int *outdeg, *indeg;
    unsigned long long* state;
    cudaGetSymbolAddress((void**)&xh, g_xh);
    cudaGetSymbolAddress((void**)&aggh, g_aggh);
    cudaGetSymbolAddress((void**)&hh, g_hh);
    cudaGetSymbolAddress((void**)&wf1, g_wfrag1);
    cudaGetSymbolAddress((void**)&wf2, g_wfrag2);
    cudaGetSymbolAddress((void**)&outdeg, g_outdeg);
    cudaGetSymbolAddress((void**)&indeg, g_indeg);
    cudaGetSymbolAddress((void**)&state, g_state);

    // Build CSR + normalization (3 memsets + 3 kernels)
    cudaMemsetAsync(outdeg, 0, N * sizeof(int));
    cudaMemsetAsync(indeg, 0, N * sizeof(int));
    cudaMemsetAsync(state, 0xFF, NBLK * sizeof(unsigned long long));
    k_deg<<<(E + 255) / 256, 256>>>(src, dst, E);
    k_scan<<<NBLK, 1024>>>(N, E);
    k_build2<<<SCAT_BLK + TOH_BLK + 32, 256>>>(src, dst, (const float4*)x, (uint2*)xh,
                                               W1, wf1, W2, wf2, E, N);

    dim3 gt(32, 8);
    int gblocks = (N + 7) / 8;
    int mblocks = (N + 127) / 128;   // 782

    // Layer 1: plain-sum gather (xh pre-scaled) -> GEMM (writes hh = prelu(..)*inv, half)
    k_gather<<<gblocks, gt>>>((const uint2*)xh, (uint2*)aggh, N);
    k_gemm_mma<true><<<mblocks, 256>>>(aggh, wf1, b1, pa, hh, N);
    // Layer 2: plain-sum gather -> GEMM (writes fp32 d_out)
    k_gather<<<gblocks, gt>>>((const uint2*)hh, (uint2*)aggh, N);
    k_gemm_mma<false><<<mblocks, 256>>>(aggh, wf2, b2, pa, out, N);
}

// round 10
// speedup vs baseline: 1.0124x; 1.0124x over previous
#include <cuda_runtime.h>
#include <cuda_fp16.h>
#include <cstdint>

#define NN 100000
#define EE 1600000
#define DD 128
#define NBLK ((NN + 1023) / 1024)   // 98 scan blocks

// ---------------- static device scratch (no allocation allowed) ----------------
__device__ __half g_xh[NN * DD];        // x * inv[row], half
__device__ __half g_aggh[NN * DD];      // gather output, half
__device__ __half g_hh[NN * DD];        // layer-1 output * inv[row], half
__device__ uint2  g_wfrag1[8 * 16 * 32];  // W1 f16 B-fragment table (32KB)
__device__ uint2  g_wfrag2[8 * 16 * 32];  // W2 fragment table
__device__ int    g_outdeg[NN];
__device__ int    g_indeg[NN];
__device__ int    g_rowptr[NN + 1];
__device__ int    g_cursor[NN];
__device__ int    g_colidx[EE];
__device__ float  g_inv[NN];
__device__ int    g_bsum[NBLK];
__device__ int    g_boff[NBLK];

#define MMA_F16(c0, c1, c2, c3, a0, a1, a2, a3, b0, b1) \
    asm volatile("mma.sync.aligned.m16n8k16.row.col.f32.f16.f16.f32 " \
        "{%0,%1,%2,%3}, {%4,%5,%6,%7}, {%8,%9}, {%0,%1,%2,%3};" \
        : "+f"(c0), "+f"(c1), "+f"(c2), "+f"(c3) \
        : "r"(a0), "r"(a1), "r"(a2), "r"(a3), "r"(b0), "r"(b1))

__device__ __forceinline__ uint32_t h2bits(__half2 h) {
    return *(uint32_t*)&h;
}

// ---------------- build: degrees ----------------
__global__ void k_deg(const int* __restrict__ src, const int* __restrict__ dst, int E) {
    int e = blockIdx.x * blockDim.x + threadIdx.x;
    if (e < E) {
        atomicAdd(&g_outdeg[src[e]], 1);
        atomicAdd(&g_indeg[dst[e]], 1);
    }
}

// ---------------- build: parallel exclusive scan (3 stages, R8 structure) ----------------
__global__ void k_scan1(int N) {
    __shared__ int s_w[32];
    int tid = threadIdx.x, lane = tid & 31, wid = tid >> 5;
    int i = blockIdx.x * 1024 + tid;
    int v = (i < N) ? g_indeg[i] : 0;
    int incl = v;
#pragma unroll
    for (int off = 1; off < 32; off <<= 1) {
        int t = __shfl_up_sync(0xffffffffu, incl, off);
        if (lane >= off) incl += t;
    }
    if (lane == 31) s_w[wid] = incl;
    __syncthreads();
    if (wid == 0) {
        int s = s_w[lane];
        int si = s;
#pragma unroll
        for (int off = 1; off < 32; off <<= 1) {
            int t = __shfl_up_sync(0xffffffffu, si, off);
            if (lane >= off) si += t;
        }
        s_w[lane] = si - s;
    }
    __syncthreads();
    int excl = incl - v + s_w[wid];
    if (i < N) g_rowptr[i] = excl;
    if (tid == 1023) g_bsum[blockIdx.x] = s_w[31] + incl;
}

__global__ void k_scan2() {
    __shared__ int s_w[4];
    int tid = threadIdx.x, lane = tid & 31, wid = tid >> 5;
    int v = (tid < NBLK) ? g_bsum[tid] : 0;
    int incl = v;
#pragma unroll
    for (int off = 1; off < 32; off <<= 1) {
        int t = __shfl_up_sync(0xffffffffu, incl, off);
        if (lane >= off) incl += t;
    }
    if (lane == 31) s_w[wid] = incl;
    __syncthreads();
    int woff = 0;
#pragma unroll
    for (int w = 0; w < 4; w++)
        if (w < wid) woff += s_w[w];
    if (tid < NBLK) g_boff[tid] = incl - v + woff;
}

__global__ void k_scan3(int N, int E) {
    int i = blockIdx.x * blockDim.x + threadIdx.x;
    if (i < N) {
        int v = g_rowptr[i] + g_boff[i >> 10];
        g_rowptr[i] = v;
        g_cursor[i] = v;
        int d = g_outdeg[i];
        g_inv[i] = 1.0f / (float)(d > 1 ? d : 1);
    }
    if (i == 0) g_rowptr[N] = E;
}

// ---------------- merged scatter + x->half ----------------
#define SCAT_BLK ((EE + 255) / 256)        // 6250
#define TOH_BLK  ((NN * 32 + 255) / 256)   // 12500
__global__ void k_scatter_tohalf(const int* __restrict__ src, const int* __restrict__ dst,
                                 const float4* __restrict__ x, uint2* __restrict__ xh,
                                 int E, int N) {
    int b = blockIdx.x;
    if (b < SCAT_BLK) {
        int e = b * 256 + threadIdx.x;
        if (e < E) {
            int p = atomicAdd(&g_cursor[dst[e]], 1);
            g_colidx[p] = src[e];
        }
    } else {
        int i = (b - SCAT_BLK) * 256 + threadIdx.x;
        if (i < N * 32) {
            float s = g_inv[i >> 5];
            float4 v = x[i];
            __half2 h01 = __floats2half2_rn(v.x * s, v.y * s);
            __half2 h23 = __floats2half2_rn(v.z * s, v.w * s);
            xh[i] = make_uint2(h2bits(h01), h2bits(h23));
        }
    }
}

// ---------------- pack both W into f16 mma B-fragment tables ----------------
__global__ void k_wfrag2x(const float* __restrict__ W1, uint2* __restrict__ f1,
                          const float* __restrict__ W2, uint2* __restrict__ f2) {
    int gb = blockIdx.x;
    const float* W = (gb < 16) ? W1 : W2;
    uint2* frag = (gb < 16) ? f1 : f2;
    int idx = (gb & 15) * 256 + threadIdx.x;   // 0..4095
    int lane = idx & 31, nt = (idx >> 5) & 15, ks = idx >> 9;
    int k0 = ks * 16, col = nt * 8 + (lane >> 2), r = lane & 3;
    __half2 b0 = __floats2half2_rn(W[(k0 + 2 * r) * DD + col], W[(k0 + 2 * r + 1) * DD + col]);
    __half2 b1 = __floats2half2_rn(W[(k0 + 2 * r + 8) * DD + col], W[(k0 + 2 * r + 9) * DD + col]);
    frag[idx] = make_uint2(h2bits(b0), h2bits(b1));
}

// ---------------- SpMM gather v2: half-warp edge pairing, uint4 loads ----------------
// Warp per node. Lanes 0-15 process even edges, 16-31 odd edges; each lane loads
// a 16B chunk (8 halves) of its edge's source row. Final shfl(16)-combine, lanes
// 0-15 write the node row as uint4.
__device__ __forceinline__ void acc8(float* a, uint4 v) {
    float2 f;
    f = __half22float2(*(__half2*)&v.x); a[0] += f.x; a[1] += f.y;
    f = __half22float2(*(__half2*)&v.y); a[2] += f.x; a[3] += f.y;
    f = __half22float2(*(__half2*)&v.z); a[4] += f.x; a[5] += f.y;
    f = __half22float2(*(__half2*)&v.w); a[6] += f.x; a[7] += f.y;
}

__global__ void k_gather(const uint4* __restrict__ xin, uint4* __restrict__ out, int N) {
    int lane = threadIdx.x;
    int node = blockIdx.x * blockDim.y + threadIdx.y;
    if (node >= N) return;
    int c = lane & 15;            // 16B chunk index within row
    bool lo = lane < 16;
    int beg = g_rowptr[node], end = g_rowptr[node + 1];

    float a0[8] = {0, 0, 0, 0, 0, 0, 0, 0};
    float a1[8] = {0, 0, 0, 0, 0, 0, 0, 0};

    int e = beg;
    // align to even edge index (solo: lanes 0-15 only)
    if ((e & 1) && e < end) {
        if (lo) {
            int s = g_colidx[e];
            acc8(a0, xin[s * 16 + c]);
        }
        e++;
    }
    // paired, unrolled x2 (4 edges/iter)
    for (; e + 4 <= end; e += 4) {
        int2 ssA = *(const int2*)(g_colidx + e);
        int2 ssB = *(const int2*)(g_colidx + e + 2);
        int sA = lo ? ssA.x : ssA.y;
        int sB = lo ? ssB.x : ssB.y;
        uint4 vA = xin[sA * 16 + c];
        uint4 vB = xin[sB * 16 + c];
        acc8(a0, vA);
        acc8(a1, vB);
    }
    // paired remainder
    if (e + 2 <= end) {
        int2 ss = *(const int2*)(g_colidx + e);
        int s = lo ? ss.x : ss.y;
        acc8(a0, xin[s * 16 + c]);
        e += 2;
    }
    // trailing solo
    if (e < end) {
        if (lo) {
            int s = g_colidx[e];
            acc8(a1, xin[s * 16 + c]);
        }
    }

#pragma unroll
    for (int j = 0; j < 8; j++) a0[j] += a1[j];
    // combine odd-edge partials (lanes 16-31) into lanes 0-15
#pragma unroll
    for (int j = 0; j < 8; j++)
        a0[j] += __shfl_down_sync(0xffffffffu, a0[j], 16);

    if (lo) {
        uint4 o;
        o.x = h2bits(__floats2half2_rn(a0[0], a0[1]));
        o.y = h2bits(__floats2half2_rn(a0[2], a0[3]));
        o.z = h2bits(__floats2half2_rn(a0[4], a0[5]));
        o.w = h2bits(__floats2half2_rn(a0[6], a0[7]));
        out[node * 16 + c] = o;
    }
}

// ---------------- f16 mma GEMM + bias + PReLU ----------------
// CTA: 128 rows x 128 cols, 8 warps, warp tile 32x64 (2 m-groups share each B frag).
#define ASTRH 136    // half stride: conflict-free A-frag LDS
template <bool HALF_OUT>
__global__ __launch_bounds__(256, 2)
void k_gemm_mma(const __half* __restrict__ A, const uint2* __restrict__ wfrag,
                const float* __restrict__ bias, const float* __restrict__ pa,
                void* __restrict__ outp, int N) {
    __shared__ __align__(16) __half As[128 * ASTRH];
    int tid = threadIdx.x;
    int lane = tid & 31, wid = tid >> 5;
    int rowgrp = wid & 3, colgrp = wid >> 2;
    int rbase = blockIdx.x * 128;

    const uint2* A2 = (const uint2*)A;
#pragma unroll 4
    for (int i = tid; i < 128 * 32; i += 256) {
        int r = i >> 5, c4 = i & 31;
        int row = rbase + r;
        if (row >= N) row = N - 1;   // clamp; extra rows never stored
        *(uint2*)&As[r * ASTRH + c4 * 4] = A2[row * 32 + c4];
    }
    __syncthreads();

    float c[2][8][4];
#pragma unroll
    for (int mg = 0; mg < 2; mg++)
#pragma unroll
        for (int nt = 0; nt < 8; nt++)
#pragma unroll
            for (int j = 0; j < 4; j++) c[mg][nt][j] = 0.f;

    const __half* Ab0 = As + (rowgrp * 32 + (lane >> 2)) * ASTRH + 2 * (lane & 3);
    const __half* Ab1 = Ab0 + 16 * ASTRH;

#pragma unroll
    for (int ks = 0; ks < 8; ks++) {
        int k0 = ks * 16;
        uint32_t a00 = *(const uint32_t*)&Ab0[k0];
        uint32_t a01 = *(const uint32_t*)&Ab0[8 * ASTRH + k0];
        uint32_t a02 = *(const uint32_t*)&Ab0[k0 + 8];
        uint32_t a03 = *(const uint32_t*)&Ab0[8 * ASTRH + k0 + 8];
        uint32_t a10 = *(const uint32_t*)&Ab1[k0];
        uint32_t a11 = *(const uint32_t*)&Ab1[8 * ASTRH + k0];
        uint32_t a12 = *(const uint32_t*)&Ab1[k0 + 8];
        uint32_t a13 = *(const uint32_t*)&Ab1[8 * ASTRH + k0 + 8];
        const uint2* wk = wfrag + (ks * 16 + colgrp * 8) * 32 + lane;
#pragma unroll
        for (int nt = 0; nt < 8; nt++) {
            uint2 bv = wk[nt * 32];
            MMA_F16(c[0][nt][0], c[0][nt][1], c[0][nt][2], c[0][nt][3],
                    a00, a01, a02, a03, bv.x, bv.y);
            MMA_F16(c[1][nt][0], c[1][nt][1], c[1][nt][2], c[1][nt][3],
                    a10, a11, a12, a13, bv.x, bv.y);
        }
    }

    float alpha = pa[0];
#pragma unroll
    for (int mg = 0; mg < 2; mg++) {
        int r_lo = rbase + rowgrp * 32 + mg * 16 + (lane >> 2);
        int r_hi = r_lo + 8;
        float s_lo = 1.f, s_hi = 1.f;
        if (HALF_OUT) {
            if (r_lo < N) s_lo = g_inv[r_lo];
            if (r_hi < N) s_hi = g_inv[r_hi];
        }
#pragma unroll
        for (int nt = 0; nt < 8; nt++) {
            int col = colgrp * 64 + nt * 8 + (lane & 3) * 2;
            float2 bb = *(const float2*)(bias + col);
            float z0 = c[mg][nt][0] + bb.x;
            float z1 = c[mg][nt][1] + bb.y;
            float z2 = c[mg][nt][2] + bb.x;
            float z3 = c[mg][nt][3] + bb.y;
            z0 = (z0 >= 0.f) ? z0 : alpha * z0;
            z1 = (z1 >= 0.f) ? z1 : alpha * z1;
            z2 = (z2 >= 0.f) ? z2 : alpha * z2;
            z3 = (z3 >= 0.f) ? z3 : alpha * z3;
            if (HALF_OUT) {
                __half* outh = (__half*)outp;
                if (r_lo < N) {
                    __half2 o = __floats2half2_rn(z0 * s_lo, z1 * s_lo);
                    *(__half2*)(outh + r_lo * DD + col) = o;
                }
                if (r_hi < N) {
                    __half2 o = __floats2half2_rn(z2 * s_hi, z3 * s_hi);
                    *(__half2*)(outh + r_hi * DD + col) = o;
                }
            } else {
                float* outf = (float*)outp;
                if (r_lo < N) { float2 o = {z0, z1}; *(float2*)(outf + r_lo * DD + col) = o; }
                if (r_hi < N) { float2 o = {z2, z3}; *(float2*)(outf + r_hi * DD + col) = o; }
            }
        }
    }
}

// ---------------- launch ----------------
extern "C" void kernel_launch(void* const* d_in, const int* in_sizes, int n_in,
                              void* d_out, int out_size) {
    const float* x   = (const float*)d_in[0];
    const int*   src = (const int*)d_in[1];
    const int*   dst = (const int*)d_in[2];
    const float* W1  = (const float*)d_in[3];
    const float* b1  = (const float*)d_in[4];
    const float* W2  = (const float*)d_in[5];
    const float* b2  = (const float*)d_in[6];
    const float* pa  = (const float*)d_in[7];
    float* out = (float*)d_out;

    const int N = NN;
    const int E = EE;

    __half *xh, *aggh, *hh;
    uint2 *wf1, *wf2;
    int *outdeg, *indeg;
    cudaGetSymbolAddress((void**)&xh, g_xh);
    cudaGetSymbolAddress((void**)&aggh, g_aggh);
    cudaGetSymbolAddress((void**)&hh, g_hh);
    cudaGetSymbolAddress((void**)&wf1, g_wfrag1);
    cudaGetSymbolAddress((void**)&wf2, g_wfrag2);
    cudaGetSymbolAddress((void**)&outdeg, g_outdeg);
    cudaGetSymbolAddress((void**)&indeg, g_indeg);

    // Build CSR + normalization (R8 structure)
    cudaMemsetAsync(outdeg, 0, N * sizeof(int));
    cudaMemsetAsync(indeg, 0, N * sizeof(int));
    k_deg<<<(E + 255) / 256, 256>>>(src, dst, E);
    k_scan1<<<NBLK, 1024>>>(N);
    k_scan2<<<1, 128>>>();
    k_scan3<<<(N + 255) / 256, 256>>>(N, E);
    k_scatter_tohalf<<<SCAT_BLK + TOH_BLK, 256>>>(src, dst, (const float4*)x, (uint2*)xh, E, N);
    k_wfrag2x<<<32, 256>>>(W1, wf1, W2, wf2);

    dim3 gt(32, 8);
    int gblocks = (N + 7) / 8;
    int mblocks = (N + 127) / 128;   // 782

    // Layer 1: plain-sum gather (xh pre-scaled) -> GEMM (writes hh = prelu(..)*inv, half)
    k_gather<<<gblocks, gt>>>((const uint4*)xh, (uint4*)aggh, N);
    k_gemm_mma<true><<<mblocks, 256>>>(aggh, wf1, b1, pa, hh, N);
    // Layer 2: plain-sum gather -> GEMM (writes fp32 d_out)
    k_gather<<<gblocks, gt>>>((const uint4*)hh, (uint4*)aggh, N);
    k_gemm_mma<false><<<mblocks, 256>>>(aggh, wf2, b2, pa, out, N);
}

// round 11
// speedup vs baseline: 1.0801x; 1.0669x over previous
#include <cuda_runtime.h>
#include <cuda_fp16.h>
#include <cstdint>

#define NN 100000
#define EE 1600000
#define DD 128
#define NBLK ((NN + 1023) / 1024)   // 98 scan blocks

// ---------------- static device scratch (no allocation allowed) ----------------
__device__ __half g_xh[NN * DD];        // x * inv[row], half
__device__ __half g_aggh[NN * DD];      // gather output, half
__device__ __half g_hh[NN * DD];        // layer-1 output * inv[row], half
__device__ uint2  g_wfrag1[8 * 16 * 32];  // W1 f16 B-fragment table (32KB)
__device__ uint2  g_wfrag2[8 * 16 * 32];  // W2 fragment table
__device__ int    g_deg[2 * NN + 1];    // [0,NN)=outdeg, [NN,2NN)=indeg, [2NN]=scan counter
__device__ int    g_rowptr[NN];         // region start per node (block-base order arbitrary)
__device__ int    g_cursor[NN];
__device__ int    g_colidx[EE];
__device__ float  g_inv[NN];

#define MMA_F16(c0, c1, c2, c3, a0, a1, a2, a3, b0, b1) \
    asm volatile("mma.sync.aligned.m16n8k16.row.col.f32.f16.f16.f32 " \
        "{%0,%1,%2,%3}, {%4,%5,%6,%7}, {%8,%9}, {%0,%1,%2,%3};" \
        : "+f"(c0), "+f"(c1), "+f"(c2), "+f"(c3) \
        : "r"(a0), "r"(a1), "r"(a2), "r"(a3), "r"(b0), "r"(b1))

__device__ __forceinline__ uint32_t h2bits(__half2 h) {
    return *(uint32_t*)&h;
}

// ---------------- build: degrees + W fragment pack (independent, one launch) ----------------
#define DEG_BLK ((EE + 255) / 256)   // 6250
__global__ void k_deg_wfrag(const int* __restrict__ src, const int* __restrict__ dst,
                            const float* __restrict__ W1, uint2* __restrict__ f1,
                            const float* __restrict__ W2, uint2* __restrict__ f2, int E) {
    int b = blockIdx.x;
    if (b < DEG_BLK) {
        int e = b * 256 + threadIdx.x;
        if (e < E) {
            atomicAdd(&g_deg[src[e]], 1);          // outdeg
            atomicAdd(&g_deg[NN + dst[e]], 1);     // indeg
        }
    } else {
        int gb = b - DEG_BLK;   // 0..31
        const float* W = (gb < 16) ? W1 : W2;
        uint2* frag = (gb < 16) ? f1 : f2;
        int idx = (gb & 15) * 256 + threadIdx.x;   // 0..4095
        int lane = idx & 31, nt = (idx >> 5) & 15, ks = idx >> 9;
        int k0 = ks * 16, col = nt * 8 + (lane >> 2), r = lane & 3;
        __half2 b0 = __floats2half2_rn(W[(k0 + 2 * r) * DD + col], W[(k0 + 2 * r + 1) * DD + col]);
        __half2 b1 = __floats2half2_rn(W[(k0 + 2 * r + 8) * DD + col], W[(k0 + 2 * r + 9) * DD + col]);
        frag[idx] = make_uint2(h2bits(b0), h2bits(b1));
    }
}

// ---------------- build: single-kernel scan (atomic block-base assignment) ----------------
// Each block scans its 1024 indeg chunk, grabs a base via atomicAdd of its total
// (order-independent: nodes only need disjoint contiguous regions), writes
// rowptr/cursor/inv. Gather uses end = rowptr + indeg.
__global__ __launch_bounds__(1024)
void k_scan(int N) {
    __shared__ int s_w[32];
    __shared__ int s_base;
    int tid = threadIdx.x, lane = tid & 31, wid = tid >> 5;
    int i = blockIdx.x * 1024 + tid;
    int v = (i < N) ? g_deg[NN + i] : 0;
    int incl = v;
#pragma unroll
    for (int off = 1; off < 32; off <<= 1) {
        int t = __shfl_up_sync(0xffffffffu, incl, off);
        if (lane >= off) incl += t;
    }
    if (lane == 31) s_w[wid] = incl;
    __syncthreads();
    if (wid == 0) {
        int s = s_w[lane];
        int si = s;
#pragma unroll
        for (int off = 1; off < 32; off <<= 1) {
            int t = __shfl_up_sync(0xffffffffu, si, off);
            if (lane >= off) si += t;
        }
        s_w[lane] = si - s;            // exclusive prefix of warp sums
        if (lane == 31) s_base = atomicAdd(&g_deg[2 * NN], si);   // si = block total
    }
    __syncthreads();
    if (i < N) {
        int val = s_base + incl - v + s_w[wid];
        g_rowptr[i] = val;
        g_cursor[i] = val;
        int d = g_deg[i];              // outdeg
        g_inv[i] = 1.0f / (float)(d > 1 ? d : 1);
    }
}

// ---------------- merged scatter + x->half ----------------
#define SCAT_BLK ((EE + 255) / 256)        // 6250
#define TOH_BLK  ((NN * 32 + 255) / 256)   // 12500
__global__ void k_scatter_tohalf(const int* __restrict__ src, const int* __restrict__ dst,
                                 const float4* __restrict__ x, uint2* __restrict__ xh,
                                 int E, int N) {
    int b = blockIdx.x;
    if (b < SCAT_BLK) {
        int e = b * 256 + threadIdx.x;
        if (e < E) {
            int p = atomicAdd(&g_cursor[dst[e]], 1);
            g_colidx[p] = src[e];
        }
    } else {
        int i = (b - SCAT_BLK) * 256 + threadIdx.x;
        if (i < N * 32) {
            float s = g_inv[i >> 5];
            float4 v = x[i];
            __half2 h01 = __floats2half2_rn(v.x * s, v.y * s);
            __half2 h23 = __floats2half2_rn(v.z * s, v.w * s);
            xh[i] = make_uint2(h2bits(h01), h2bits(h23));
        }
    }
}

// ---------------- SpMM gather: R8 layout + pairwise HADD2 ----------------
// Warp per node, lane owns 4 halves (uint2). Edge pairs summed in half (HADD2)
// before fp32 accumulation: ~37% fewer arith instrs per edge.
__device__ __forceinline__ void accpair(float4& a, uint2 v0, uint2 v1) {
    __half2 ha = __hadd2(*(__half2*)&v0.x, *(__half2*)&v1.x);
    __half2 hb = __hadd2(*(__half2*)&v0.y, *(__half2*)&v1.y);
    float2 f;
    f = __half22float2(ha); a.x += f.x; a.y += f.y;
    f = __half22float2(hb); a.z += f.x; a.w += f.y;
}
__device__ __forceinline__ void accsolo(float4& a, uint2 v) {
    float2 f;
    f = __half22float2(*(__half2*)&v.x); a.x += f.x; a.y += f.y;
    f = __half22float2(*(__half2*)&v.y); a.z += f.x; a.w += f.y;
}

__global__ void k_gather(const uint2* __restrict__ xin, uint2* __restrict__ out, int N) {
    int lane = threadIdx.x;
    int node = blockIdx.x * blockDim.y + threadIdx.y;
    if (node >= N) return;
    int beg = g_rowptr[node];
    int end = beg + g_deg[NN + node];   // indeg
    float4 a0 = make_float4(0.f, 0.f, 0.f, 0.f);
    float4 a1 = make_float4(0.f, 0.f, 0.f, 0.f);
    int e = beg;
    if ((e & 1) && e < end) {           // align to even for int2 loads
        accsolo(a0, xin[g_colidx[e] * 32 + lane]);
        e++;
    }
#pragma unroll 1
    for (; e + 4 <= end; e += 4) {
        int2 sA = *(const int2*)(g_colidx + e);
        int2 sB = *(const int2*)(g_colidx + e + 2);
        uint2 v0 = xin[sA.x * 32 + lane];
        uint2 v1 = xin[sA.y * 32 + lane];
        uint2 v2 = xin[sB.x * 32 + lane];
        uint2 v3 = xin[sB.y * 32 + lane];
        accpair(a0, v0, v1);
        accpair(a1, v2, v3);
    }
    if (e + 2 <= end) {
        int2 s = *(const int2*)(g_colidx + e);
        uint2 v0 = xin[s.x * 32 + lane];
        uint2 v1 = xin[s.y * 32 + lane];
        accpair(a0, v0, v1);
        e += 2;
    }
    if (e < end)
        accsolo(a1, xin[g_colidx[e] * 32 + lane]);

    a0.x += a1.x; a0.y += a1.y; a0.z += a1.z; a0.w += a1.w;
    __half2 h01 = __floats2half2_rn(a0.x, a0.y);
    __half2 h23 = __floats2half2_rn(a0.z, a0.w);
    out[node * 32 + lane] = make_uint2(h2bits(h01), h2bits(h23));
}

// ---------------- f16 mma GEMM + bias + PReLU ----------------
// CTA: 128 rows x 128 cols, 8 warps, warp tile 32x64 (2 m-groups share each B frag).
#define ASTRH 136    // half stride: conflict-free A-frag LDS
template <bool HALF_OUT>
__global__ __launch_bounds__(256, 2)
void k_gemm_mma(const __half* __restrict__ A, const uint2* __restrict__ wfrag,
                const float* __restrict__ bias, const float* __restrict__ pa,
                void* __restrict__ outp, int N) {
    __shared__ __align__(16) __half As[128 * ASTRH];
    int tid = threadIdx.x;
    int lane = tid & 31, wid = tid >> 5;
    int rowgrp = wid & 3, colgrp = wid >> 2;
    int rbase = blockIdx.x * 128;

    const uint2* A2 = (const uint2*)A;
#pragma unroll 4
    for (int i = tid; i < 128 * 32; i += 256) {
        int r = i >> 5, c4 = i & 31;
        int row = rbase + r;
        if (row >= N) row = N - 1;   // clamp; extra rows never stored
        *(uint2*)&As[r * ASTRH + c4 * 4] = A2[row * 32 + c4];
    }
    __syncthreads();

    float c[2][8][4];
#pragma unroll
    for (int mg = 0; mg < 2; mg++)
#pragma unroll
        for (int nt = 0; nt < 8; nt++)
#pragma unroll
            for (int j = 0; j < 4; j++) c[mg][nt][j] = 0.f;

    const __half* Ab0 = As + (rowgrp * 32 + (lane >> 2)) * ASTRH + 2 * (lane & 3);
    const __half* Ab1 = Ab0 + 16 * ASTRH;

#pragma unroll
    for (int ks = 0; ks < 8; ks++) {
        int k0 = ks * 16;
        uint32_t a00 = *(const uint32_t*)&Ab0[k0];
        uint32_t a01 = *(const uint32_t*)&Ab0[8 * ASTRH + k0];
        uint32_t a02 = *(const uint32_t*)&Ab0[k0 + 8];
        uint32_t a03 = *(const uint32_t*)&Ab0[8 * ASTRH + k0 + 8];
        uint32_t a10 = *(const uint32_t*)&Ab1[k0];
        uint32_t a11 = *(const uint32_t*)&Ab1[8 * ASTRH + k0];
        uint32_t a12 = *(const uint32_t*)&Ab1[k0 + 8];
        uint32_t a13 = *(const uint32_t*)&Ab1[8 * ASTRH + k0 + 8];
        const uint2* wk = wfrag + (ks * 16 + colgrp * 8) * 32 + lane;
#pragma unroll
        for (int nt = 0; nt < 8; nt++) {
            uint2 bv = wk[nt * 32];
            MMA_F16(c[0][nt][0], c[0][nt][1], c[0][nt][2], c[0][nt][3],
                    a00, a01, a02, a03, bv.x, bv.y);
            MMA_F16(c[1][nt][0], c[1][nt][1], c[1][nt][2], c[1][nt][3],
                    a10, a11, a12, a13, bv.x, bv.y);
        }
    }

    float alpha = pa[0];
#pragma unroll
    for (int mg = 0; mg < 2; mg++) {
        int r_lo = rbase + rowgrp * 32 + mg * 16 + (lane >> 2);
        int r_hi = r_lo + 8;
        float s_lo = 1.f, s_hi = 1.f;
        if (HALF_OUT) {
            if (r_lo < N) s_lo = g_inv[r_lo];
            if (r_hi < N) s_hi = g_inv[r_hi];
        }
#pragma unroll
        for (int nt = 0; nt < 8; nt++) {
            int col = colgrp * 64 + nt * 8 + (lane & 3) * 2;
            float2 bb = *(const float2*)(bias + col);
            float z0 = c[mg][nt][0] + bb.x;
            float z1 = c[mg][nt][1] + bb.y;
            float z2 = c[mg][nt][2] + bb.x;
            float z3 = c[mg][nt][3] + bb.y;
            z0 = (z0 >= 0.f) ? z0 : alpha * z0;
            z1 = (z1 >= 0.f) ? z1 : alpha * z1;
            z2 = (z2 >= 0.f) ? z2 : alpha * z2;
            z3 = (z3 >= 0.f) ? z3 : alpha * z3;
            if (HALF_OUT) {
                __half* outh = (__half*)outp;
                if (r_lo < N) {
                    __half2 o = __floats2half2_rn(z0 * s_lo, z1 * s_lo);
                    *(__half2*)(outh + r_lo * DD + col) = o;
                }
                if (r_hi < N) {
                    __half2 o = __floats2half2_rn(z2 * s_hi, z3 * s_hi);
                    *(__half2*)(outh + r_hi * DD + col) = o;
                }
            } else {
                float* outf = (float*)outp;
                if (r_lo < N) { float2 o = {z0, z1}; *(float2*)(outf + r_lo * DD + col) = o; }
                if (r_hi < N) { float2 o = {z2, z3}; *(float2*)(outf + r_hi * DD + col) = o; }
            }
        }
    }
}

// ---------------- launch ----------------
extern "C" void kernel_launch(void* const* d_in, const int* in_sizes, int n_in,
                              void* d_out, int out_size) {
    const float* x   = (const float*)d_in[0];
    const int*   src = (const int*)d_in[1];
    const int*   dst = (const int*)d_in[2];
    const float* W1  = (const float*)d_in[3];
    const float* b1  = (const float*)d_in[4];
    const float* W2  = (const float*)d_in[5];
    const float* b2  = (const float*)d_in[6];
    const float* pa  = (const float*)d_in[7];
    float* out = (float*)d_out;

    const int N = NN;
    const int E = EE;

    __half *xh, *aggh, *hh;
    uint2 *wf1, *wf2;
    int *deg;
    cudaGetSymbolAddress((void**)&xh, g_xh);
    cudaGetSymbolAddress((void**)&aggh, g_aggh);
    cudaGetSymbolAddress((void**)&hh, g_hh);
    cudaGetSymbolAddress((void**)&wf1, g_wfrag1);
    cudaGetSymbolAddress((void**)&wf2, g_wfrag2);
    cudaGetSymbolAddress((void**)&deg, g_deg);

    // Build: 1 memset + 3 kernels
    cudaMemsetAsync(deg, 0, (2 * N + 1) * sizeof(int));
    k_deg_wfrag<<<DEG_BLK + 32, 256>>>(src, dst, W1, wf1, W2, wf2, E);
    k_scan<<<NBLK, 1024>>>(N);
    k_scatter_tohalf<<<SCAT_BLK + TOH_BLK, 256>>>(src, dst, (const float4*)x, (uint2*)xh, E, N);

    dim3 gt(32, 8);
    int gblocks = (N + 7) / 8;
    int mblocks = (N + 127) / 128;   // 782

    // Layer 1: plain-sum gather (xh pre-scaled) -> GEMM (writes hh = prelu(..)*inv, half)
    k_gather<<<gblocks, gt>>>((const uint2*)xh, (uint2*)aggh, N);
    k_gemm_mma<true><<<mblocks, 256>>>(aggh, wf1, b1, pa, hh, N);
    // Layer 2: plain-sum gather -> GEMM (writes fp32 d_out)
    k_gather<<<gblocks, gt>>>((const uint2*)hh, (uint2*)aggh, N);
    k_gemm_mma<false><<<mblocks, 256>>>(aggh, wf2, b2, pa, out, N);
}